// round 2
// baseline (speedup 1.0000x reference)
#include <cuda_runtime.h>
#include <cuda_bf16.h>

// Max pairs for insnum=3000: 3000*3000-3000 = 8,997,000. Round up.
#define MAX_PAIRS 9000000

// Static scratch: one byte per pair row, low 4 bits = class-bit mask.
__device__ unsigned char g_mask[MAX_PAIRS];

// ---------------------------------------------------------------------------
// type table: _SUPPORT -> 1, _PROXIMITY -> 2, _COMPARATIVE -> 3, else 0
// ---------------------------------------------------------------------------
__device__ __forceinline__ int type_of_pred(int p) {
    // p already clipped to [0,63]
    if (p == 1 || (p >= 14 && p <= 26)) return 1;
    if (p >= 2 && p <= 7)               return 2;
    if (p >= 8 && p <= 13)              return 3;
    return 0;
}

// ---------------------------------------------------------------------------
// Kernel 1: zero the mask array (as uint4) and the output scalar.
// ---------------------------------------------------------------------------
__global__ void zero_kernel(int n_words16, float* __restrict__ out) {
    int i = blockIdx.x * blockDim.x + threadIdx.x;
    uint4 z = make_uint4(0u, 0u, 0u, 0u);
    uint4* m = reinterpret_cast<uint4*>(g_mask);
    for (; i < n_words16; i += gridDim.x * blockDim.x) {
        m[i] = z;
    }
    if (blockIdx.x == 0 && threadIdx.x == 0) {
        *out = 0.0f;
    }
}

// ---------------------------------------------------------------------------
// Kernel 2: scatter relation class bits into the mask.
// ---------------------------------------------------------------------------
__global__ void scatter_kernel(const int* __restrict__ rel, int n_rel,
                               int insnum, int n_pairs) {
    int r = blockIdx.x * blockDim.x + threadIdx.x;
    if (r >= n_rel) return;
    int i = rel[3 * r + 0];
    int j = rel[3 * r + 1];
    int p = rel[3 * r + 2];
    if (i == j) return;
    p = min(max(p, 0), 63);
    int t = type_of_pred(p);
    long long flat = (long long)i * (insnum - 1) + j - (i < j ? 1 : 0);
    if ((unsigned long long)flat >= (unsigned long long)n_pairs) return;
    unsigned int* word = reinterpret_cast<unsigned int*>(g_mask) + (flat >> 2);
    unsigned int bit = (1u << t) << ((flat & 3) * 8);
    atomicOr(word, bit);
}

// ---------------------------------------------------------------------------
// Kernel 3: per-row focal loss + reduction.
//   log_softmax over 4 logits, p = sum of softmax probs over set class bits,
//   alpha = sum of pred_w over set class bits,
//   loss = -alpha * (1-p)^2 * log(p); mean over n_pairs.
// ---------------------------------------------------------------------------
__global__ void loss_kernel(const float4* __restrict__ logits,
                            const float* __restrict__ pred_w,
                            float* __restrict__ out,
                            int n_pairs, float inv_n) {
    const float a0 = __ldg(&pred_w[0]);
    const float a1 = __ldg(&pred_w[1]);
    const float a2 = __ldg(&pred_w[2]);
    const float a3 = __ldg(&pred_w[3]);

    float acc = 0.0f;
    for (int r = blockIdx.x * blockDim.x + threadIdx.x; r < n_pairs;
         r += gridDim.x * blockDim.x) {
        float4 x = __ldg(&logits[r]);
        unsigned int m = __ldg(&g_mask[r]);
        if (m == 0u) m = 1u;  // empty row -> class 0

        float mx = fmaxf(fmaxf(x.x, x.y), fmaxf(x.z, x.w));
        float e0 = __expf(x.x - mx);
        float e1 = __expf(x.y - mx);
        float e2 = __expf(x.z - mx);
        float e3 = __expf(x.w - mx);
        float S = e0 + e1 + e2 + e3;

        float ms = 0.0f, alpha = 0.0f;
        if (m & 1u) { ms += e0; alpha += a0; }
        if (m & 2u) { ms += e1; alpha += a1; }
        if (m & 4u) { ms += e2; alpha += a2; }
        if (m & 8u) { ms += e3; alpha += a3; }

        float p  = ms / S;
        float om = 1.0f - p;
        acc += -alpha * om * om * __logf(p);
    }

    // warp reduce
    #pragma unroll
    for (int o = 16; o > 0; o >>= 1)
        acc += __shfl_xor_sync(0xffffffffu, acc, o);

    __shared__ float smem[32];
    int lane = threadIdx.x & 31;
    int wid  = threadIdx.x >> 5;
    if (lane == 0) smem[wid] = acc;
    __syncthreads();

    int nwarps = blockDim.x >> 5;
    if (wid == 0) {
        float v = (lane < nwarps) ? smem[lane] : 0.0f;
        #pragma unroll
        for (int o = 16; o > 0; o >>= 1)
            v += __shfl_xor_sync(0xffffffffu, v, o);
        if (lane == 0)
            atomicAdd(out, v * inv_n);
    }
}

// ---------------------------------------------------------------------------
// Launch
// ---------------------------------------------------------------------------
extern "C" void kernel_launch(void* const* d_in, const int* in_sizes, int n_in,
                              void* d_out, int out_size) {
    const float* type_output = (const float*)d_in[0];
    const int*   rel_gt      = (const int*)d_in[2];
    const float* pred_w      = (const float*)d_in[3];

    int insnum  = in_sizes[1];
    int n_rel   = in_sizes[2] / 3;
    long long n_pairs_ll = (long long)insnum * insnum - insnum;
    int n_pairs = (n_pairs_ll > MAX_PAIRS) ? MAX_PAIRS : (int)n_pairs_ll;

    float* out = (float*)d_out;

    // 1) zero mask + output
    int n_words16 = (n_pairs + 15) / 16;
    {
        int threads = 256;
        int blocks = (n_words16 + threads - 1) / threads;
        if (blocks > 2368) blocks = 2368;
        zero_kernel<<<blocks, threads>>>(n_words16, out);
    }

    // 2) scatter class bits
    {
        int threads = 256;
        int blocks = (n_rel + threads - 1) / threads;
        scatter_kernel<<<blocks, threads>>>(rel_gt, n_rel, insnum, n_pairs);
    }

    // 3) focal loss + reduction
    {
        int threads = 256;
        int blocks = (n_pairs + threads - 1) / threads;
        if (blocks > 2368) blocks = 2368;  // ~16 blocks/SM on 148 SMs
        loss_kernel<<<blocks, threads>>>(
            (const float4*)type_output, pred_w, out,
            n_pairs, 1.0f / (float)n_pairs_ll);
    }
}